// round 6
// baseline (speedup 1.0000x reference)
#include <cuda_runtime.h>
#include <math.h>

#define B_ 8
#define N_ 2048
#define K_ 4
#define CB 512
#define PP 8
#define TMK 128
#define TNK 128

typedef unsigned long long ull;

#define FFMA2(d,a,b) asm("fma.rn.f32x2 %0, %1, %2, %0;" : "+l"(d) : "l"(a), "l"(b))
#define ADD2(d,a,b)  asm("add.rn.f32x2 %0, %1, %2;" : "=l"(d) : "l"(a), "l"(b))
__device__ __forceinline__ ull pack2(float lo, float hi) {
    ull r; asm("mov.b64 %0, {%1,%2};" : "=l"(r) : "f"(lo), "f"(hi)); return r;
}
__device__ __forceinline__ float2 unpack2(ull v) {
    float2 f; asm("mov.b64 {%0,%1}, %2;" : "=f"(f.x), "=f"(f.y) : "l"(v)); return f;
}

// top-4 insertion, strict > (stable: earlier-inserted wins ties)
__device__ __forceinline__ void ins4(float (&v)[4], int (&ix)[4], float p, int m) {
    if (p > v[3]) {
        if (p > v[1]) {
            if (p > v[0]) { v[3]=v[2];ix[3]=ix[2]; v[2]=v[1];ix[2]=ix[1]; v[1]=v[0];ix[1]=ix[0]; v[0]=p;ix[0]=m; }
            else          { v[3]=v[2];ix[3]=ix[2]; v[2]=v[1];ix[2]=ix[1]; v[1]=p;ix[1]=m; }
        } else {
            if (p > v[2]) { v[3]=v[2];ix[3]=ix[2]; v[2]=p;ix[2]=m; }
            else          { v[3]=p;ix[3]=m; }
        }
    }
}
__device__ __forceinline__ bool lexgt(float pv, int pi, float qv, int qi) {
    return (pv > qv) || (pv == qv && pi < qi);
}
__device__ __forceinline__ void ins4lex(float (&v)[4], int (&ix)[4], float p, int m) {
    if (lexgt(p, m, v[3], ix[3])) {
        if (lexgt(p, m, v[1], ix[1])) {
            if (lexgt(p, m, v[0], ix[0])) { v[3]=v[2];ix[3]=ix[2]; v[2]=v[1];ix[2]=ix[1]; v[1]=v[0];ix[1]=ix[0]; v[0]=p;ix[0]=m; }
            else                          { v[3]=v[2];ix[3]=ix[2]; v[2]=v[1];ix[2]=ix[1]; v[1]=p;ix[1]=m; }
        } else {
            if (lexgt(p, m, v[2], ix[2])) { v[3]=v[2];ix[3]=ix[2]; v[2]=p;ix[2]=m; }
            else                          { v[3]=p;ix[3]=m; }
        }
    }
}

// ---------------- scratch ----------------
__device__ float  g_xcn[(size_t)B_*CB*N_];   // [B][C][N]
__device__ float  g_xnc[(size_t)B_*N_*CB];   // [B][N][C]
__device__ float4 g_x0nc[(size_t)B_*N_];     // input [B][N][4]
__device__ float  g_xx[(size_t)B_*N_];
__device__ int4   g_idx4[(size_t)B_*N_];
__device__ float  g_uv[(size_t)B_*N_*512];   // UV per stage; y5 for conv5
__device__ float  g_mx[(size_t)B_*N_*256];
__device__ float  g_mn[(size_t)B_*N_*256];
__device__ float  g_sum[5*512];
__device__ float  g_ssq[5*512];
__device__ float4 g_wT4[90112];              // packed [c4][O2] per stage

// ---------------- prep: pack weights combined [c4][2O] + clear stats ----------------
__global__ void k_prep_w_all(const float* __restrict__ w1, const float* __restrict__ w2,
                             const float* __restrict__ w3, const float* __restrict__ w4,
                             const float* __restrict__ w5) {
    int t = blockIdx.x*blockDim.x + threadIdx.x;
    if (t < 5*512) { g_sum[t] = 0.f; g_ssq[t] = 0.f; }
    if (t >= 88192) return;
    const float* w; int realC, O, parts, lt;
    if      (t < 128)   { w = w1; realC = 3;   O = 64;  parts = 2; lt = t; }
    else if (t < 2176)  { w = w2; realC = 64;  O = 64;  parts = 2; lt = t - 128; }
    else if (t < 6272)  { w = w3; realC = 64;  O = 128; parts = 2; lt = t - 2176; }
    else if (t < 22656) { w = w4; realC = 128; O = 256; parts = 2; lt = t - 6272; }
    else                { w = w5; realC = 512; O = 512; parts = 1; lt = t - 22656; }
    int O2 = parts * O;
    int o2 = lt % O2; int c4 = lt / O2;
    int part = (o2 >= O) ? 1 : 0; int oc = o2 - part*O;
    float4 v; float* pv = (float*)&v;
    #pragma unroll
    for (int j = 0; j < 4; j++) {
        int c = c4*4 + j;
        pv[j] = (c < realC) ? w[oc*(parts*realC) + part*realC + c] : 0.f;
    }
    g_wT4[t] = v;
}

__global__ void k_prep_x0(const float* __restrict__ x) {
    int t = blockIdx.x*blockDim.x + threadIdx.x;
    if (t >= B_*N_) return;
    int b = t >> 11, n = t & (N_-1);
    float vx = x[(b*3+0)*N_ + n];
    float vy = x[(b*3+1)*N_ + n];
    float vz = x[(b*3+2)*N_ + n];
    g_x0nc[t] = make_float4(vx, vy, vz, 0.f);
    g_xx[t] = vx*vx + vy*vy + vz*vz;
}

// ---------------- knn: A resident, B double-buffered, batch-max top-4 ----------------
template<int C>
__global__ void __launch_bounds__(256) k_knn(const float* __restrict__ base, long bstride) {
    constexpr int KCc = (C < 16) ? 4 : 16;
    constexpr int NCH = (C + KCc - 1)/KCc;
    constexpr int CP  = NCH*KCc;
    constexpr int NG  = (N_/TNK)*NCH;
    extern __shared__ char smraw[];
    float* Ash = (float*)smraw;                                    // [CP][TMK]
    ull*   Bsh = (ull*)(smraw + (size_t)CP*TMK*4);                 // [2][KCc][TNK]
    ull*   nxc = (ull*)(smraw + (size_t)CP*TMK*4 + 2*KCc*TNK*8);   // [2][TNK] packed (-xx,-xx)
    const int b  = blockIdx.y;
    const int n0 = blockIdx.x * TMK;
    const float* X = base + (long)b*bstride;
    const float* xxg = g_xx + b*N_;
    const int tid = threadIdx.x;
    const int ty = tid >> 3, tx = tid & 7;
    const int r0 = ty*4;

    // full A panel, loaded once
    #pragma unroll
    for (int t = tid; t < CP*TMK; t += 256) {
        int c = t >> 7, r = t & 127;
        Ash[t] = (c < C) ? X[(long)c*N_ + n0 + r] : 0.f;
    }
    float xxr[4];
    #pragma unroll
    for (int i = 0; i < 4; i++) xxr[i] = xxg[n0 + r0 + i];
    const ull nxr01 = pack2(-xxr[0], -xxr[1]);
    const ull nxr23 = pack2(-xxr[2], -xxr[3]);
    const ull two2  = pack2(2.f, 2.f);

    float cv[4][4]; int ci[4][4];
    #pragma unroll
    for (int r = 0; r < 4; r++)
        #pragma unroll
        for (int q = 0; q < 4; q++) { cv[r][q] = -3.4e38f; ci[r][q] = 0; }

    // initial B chunk (g=0: mb=0, ch=0)
    #pragma unroll
    for (int t = tid; t < KCc*TNK; t += 256) {
        int c = t >> 7, m = t & 127;
        float v = (c < C) ? X[(long)c*N_ + m] : 0.f;
        Bsh[t] = pack2(v, v);
    }
    if (tid < TNK) { float v = xxg[tid]; nxc[tid] = pack2(-v, -v); }
    __syncthreads();

    ull acc0[16], acc1[16];
    #pragma unroll
    for (int j = 0; j < 16; j++) { acc0[j] = 0ull; acc1[j] = 0ull; }

    for (int g = 0; g < NG; g++) {
        const int mb = g / NCH, ch = g - mb*NCH;
        // prefetch chunk g+1 into other buffer
        if (g + 1 < NG) {
            const int mb1 = (g+1)/NCH, ch1 = (g+1) - mb1*NCH;
            const int m01 = mb1*TNK;
            ull* bd = Bsh + ((g+1)&1)*(KCc*TNK);
            #pragma unroll
            for (int t = tid; t < KCc*TNK; t += 256) {
                int c = t >> 7, m = t & 127;
                int cg = ch1*KCc + c;
                float v = (cg < C) ? X[(long)cg*N_ + m01 + m] : 0.f;
                bd[t] = pack2(v, v);
            }
            if (ch1 == 0 && tid < TNK) {
                float v = xxg[m01 + tid];
                nxc[(mb1&1)*TNK + tid] = pack2(-v, -v);
            }
        }
        // compute chunk g
        const ull* bb0 = Bsh + (g&1)*(KCc*TNK);
        #pragma unroll
        for (int cc = 0; cc < KCc; cc++) {
            ulonglong2 aA = *(const ulonglong2*)&Ash[(ch*KCc + cc)*TMK + r0];
            const ull* bp = bb0 + cc*TNK + tx;
            #pragma unroll
            for (int j = 0; j < 16; j++) {
                ull bbv = bp[j*8];
                FFMA2(acc0[j], aA.x, bbv);
                FFMA2(acc1[j], aA.y, bbv);
            }
        }
        if (ch == NCH - 1) {
            const ull* nxb = nxc + (mb&1)*TNK;
            const int m0 = mb*TNK;
            // fast path: packed pd + per-row max over the 16 columns
            float mx0 = -3.4e38f, mx1 = -3.4e38f, mx2 = -3.4e38f, mx3 = -3.4e38f;
            #pragma unroll
            for (int j = 0; j < 16; j++) {
                ull nx = nxb[j*8 + tx];
                ull t0 = nxr01; FFMA2(t0, acc0[j], two2);   // 2*acc - xxr (rows 0,1)
                ull p0; ADD2(p0, t0, nx);                   //  - xc
                float2 u0 = unpack2(p0);
                mx0 = fmaxf(mx0, u0.x); mx1 = fmaxf(mx1, u0.y);
                ull t1 = nxr23; FFMA2(t1, acc1[j], two2);   // rows 2,3
                ull p1; ADD2(p1, t1, nx);
                float2 u1 = unpack2(p1);
                mx2 = fmaxf(mx2, u1.x); mx3 = fmaxf(mx3, u1.y);
            }
            // slow path per row only if some candidate can insert (exact, strict >)
            if (mx0 > cv[0][3]) {
                #pragma unroll
                for (int j = 0; j < 16; j++) {
                    float2 va = unpack2(acc0[j]);
                    float2 nc = unpack2(nxb[j*8 + tx]);
                    float p = fmaf(2.f, va.x, -xxr[0]) + nc.x;
                    ins4(cv[0], ci[0], p, m0 + j*8 + tx);
                }
            }
            if (mx1 > cv[1][3]) {
                #pragma unroll
                for (int j = 0; j < 16; j++) {
                    float2 va = unpack2(acc0[j]);
                    float2 nc = unpack2(nxb[j*8 + tx]);
                    float p = fmaf(2.f, va.y, -xxr[1]) + nc.x;
                    ins4(cv[1], ci[1], p, m0 + j*8 + tx);
                }
            }
            if (mx2 > cv[2][3]) {
                #pragma unroll
                for (int j = 0; j < 16; j++) {
                    float2 vb = unpack2(acc1[j]);
                    float2 nc = unpack2(nxb[j*8 + tx]);
                    float p = fmaf(2.f, vb.x, -xxr[2]) + nc.x;
                    ins4(cv[2], ci[2], p, m0 + j*8 + tx);
                }
            }
            if (mx3 > cv[3][3]) {
                #pragma unroll
                for (int j = 0; j < 16; j++) {
                    float2 vb = unpack2(acc1[j]);
                    float2 nc = unpack2(nxb[j*8 + tx]);
                    float p = fmaf(2.f, vb.y, -xxr[3]) + nc.x;
                    ins4(cv[3], ci[3], p, m0 + j*8 + tx);
                }
            }
            #pragma unroll
            for (int j = 0; j < 16; j++) { acc0[j] = 0ull; acc1[j] = 0ull; }
        }
        __syncthreads();
    }
    // butterfly merge across the 8 column-lanes (lex: order-independent)
    #pragma unroll
    for (int st = 1; st <= 4; st <<= 1) {
        #pragma unroll
        for (int r = 0; r < 4; r++) {
            float pv[4]; int pi[4];
            #pragma unroll
            for (int q = 0; q < 4; q++) {
                pv[q] = __shfl_xor_sync(0xffffffffu, cv[r][q], st);
                pi[q] = __shfl_xor_sync(0xffffffffu, ci[r][q], st);
            }
            #pragma unroll
            for (int q = 0; q < 4; q++) ins4lex(cv[r], ci[r], pv[q], pi[q]);
        }
    }
    if (tx == 0) {
        #pragma unroll
        for (int r = 0; r < 4; r++)
            g_idx4[b*N_ + n0 + r0 + r] = make_int4(ci[r][0], ci[r][1], ci[r][2], ci[r][3]);
    }
}

// ---------------- generic GEMM: out[pt][O2] = src[pt][C] * W[C][O2] ----------------
template<int TN>
__global__ void __launch_bounds__(256) k_gemm(const float* __restrict__ src, int CS, int coff,
                                              int C, int c4n, const float4* __restrict__ wb,
                                              int O2, float* __restrict__ out) {
    constexpr int CT = TN/16;
    __shared__ float Ash[16*132];
    __shared__ ull   Bsh[16*TN];
    const int pt0 = blockIdx.x * 128;
    const int ob0 = blockIdx.y * TN;
    const int tid = threadIdx.x;
    const int ty = tid >> 4, tx = tid & 15;
    const int r0 = ty*8;

    ull acc[4][CT];
    #pragma unroll
    for (int p = 0; p < 4; p++)
        #pragma unroll
        for (int j = 0; j < CT; j++) acc[p][j] = 0ull;

    const int C16 = (C + 15) & ~15;
    for (int kc = 0; kc < C16; kc += 16) {
        #pragma unroll
        for (int t = tid; t < 16*128; t += 256) {
            int c = t & 15, r = t >> 4;
            float v = (kc + c < C) ? src[(long)(pt0 + r)*CS + coff + kc + c] : 0.f;
            Ash[c*132 + r] = v;
        }
        #pragma unroll
        for (int t = tid; t < 4*TN; t += 256) {
            int q = t / TN, o = t - q*TN;
            int c4 = (kc >> 2) + q;
            float4 w = (c4 < c4n) ? wb[(long)c4*O2 + ob0 + o] : make_float4(0.f,0.f,0.f,0.f);
            Bsh[(4*q+0)*TN + o] = pack2(w.x, w.x);
            Bsh[(4*q+1)*TN + o] = pack2(w.y, w.y);
            Bsh[(4*q+2)*TN + o] = pack2(w.z, w.z);
            Bsh[(4*q+3)*TN + o] = pack2(w.w, w.w);
        }
        __syncthreads();
        #pragma unroll
        for (int cc = 0; cc < 16; cc++) {
            ulonglong2 aA = *(const ulonglong2*)&Ash[cc*132 + r0];
            ulonglong2 aB = *(const ulonglong2*)&Ash[cc*132 + r0 + 4];
            const ull* bp = &Bsh[cc*TN + tx];
            #pragma unroll
            for (int j = 0; j < CT; j++) {
                ull bb = bp[j*16];
                FFMA2(acc[0][j], aA.x, bb);
                FFMA2(acc[1][j], aA.y, bb);
                FFMA2(acc[2][j], aB.x, bb);
                FFMA2(acc[3][j], aB.y, bb);
            }
        }
        __syncthreads();
    }
    #pragma unroll
    for (int p = 0; p < 4; p++) {
        long rowL = (long)(pt0 + r0 + 2*p) * O2 + ob0 + tx;
        #pragma unroll
        for (int j = 0; j < CT; j++) {
            float2 u = unpack2(acc[p][j]);
            out[rowL + j*16]      = u.x;
            out[rowL + O2 + j*16] = u.y;
        }
    }
}

// ---------------- gather + minmax over k + stats ----------------
__global__ void k_edge_max(const float* __restrict__ uv, int O, int O2, int stage) {
    __shared__ int sidx[PP*K_];
    const int blk = blockIdx.x;
    const int pt0 = blk * PP;
    const int o = threadIdx.x;
    const int b = pt0 >> 11;
    if (o < PP) ((int4*)sidx)[o] = g_idx4[pt0 + o];
    __syncthreads();
    float s1 = 0.f, s2 = 0.f;
    #pragma unroll
    for (int p = 0; p < PP; p++) {
        float v = uv[(long)(pt0 + p)*O2 + O + o];
        float mx = -3.4e38f, mn = 3.4e38f;
        #pragma unroll
        for (int k = 0; k < K_; k++) {
            int nb = sidx[p*K_ + k];
            float u = uv[(long)(b*N_ + nb)*O2 + o];
            float y = u + v;
            mx = fmaxf(mx, y); mn = fminf(mn, y);
            s1 += y; s2 += y*y;
        }
        g_mx[(long)(pt0 + p)*O + o] = mx;
        g_mn[(long)(pt0 + p)*O + o] = mn;
    }
    atomicAdd(&g_sum[stage*512 + o], s1);
    atomicAdd(&g_ssq[stage*512 + o], s2);
}

// ---------------- BN finalize + relu + both layouts + next-stage norms ----------------
__global__ void k_fin_edge(int O, int coff, int stage, const float* __restrict__ gm,
                           const float* __restrict__ bt, float invcnt) {
    __shared__ float wsum[8];
    const int bn = blockIdx.x;
    const int o  = threadIdx.x;
    const int so = stage*512 + o;
    float mean = g_sum[so] * invcnt;
    float var  = g_ssq[so] * invcnt - mean*mean;
    float a  = gm[o] * rsqrtf(var + 1e-5f);
    float c0 = bt[o] - mean*a;
    long t = (long)bn*O + o;
    float z = (a >= 0.f) ? (a*g_mx[t] + c0) : (a*g_mn[t] + c0);
    z = fmaxf(z, 0.f);
    int b = bn >> 11, n = bn & (N_-1);
    g_xnc[(long)bn*CB + coff + o] = z;
    g_xcn[((long)b*CB + coff + o)*N_ + n] = z;
    float r = z*z;
    #pragma unroll
    for (int d = 16; d; d >>= 1) r += __shfl_xor_sync(0xffffffffu, r, d);
    if ((o & 31) == 0) wsum[o >> 5] = r;
    __syncthreads();
    if (o == 0) {
        float s = 0.f;
        #pragma unroll
        for (int w = 0; w < 8; w++) if (w < (O >> 5)) s += wsum[w];
        g_xx[bn] = s;
    }
}

// ---------------- conv5 stats over y5 ----------------
__global__ void __launch_bounds__(512) k_stats5() {
    const int o = threadIdx.x;
    const int p0 = blockIdx.x * 128;
    float s1 = 0.f, s2 = 0.f;
    for (int i = 0; i < 128; i++) {
        float y = g_uv[(long)(p0 + i)*CB + o];
        s1 += y; s2 += y*y;
    }
    atomicAdd(&g_sum[4*512 + o], s1);
    atomicAdd(&g_ssq[4*512 + o], s2);
}

__global__ void k_fin5(const float* __restrict__ gm, const float* __restrict__ bt,
                       float* __restrict__ out) {
    __shared__ float tile[32][33];
    const int b  = blockIdx.z;
    const int o0 = blockIdx.y*32;
    const int n0 = blockIdx.x*32;
    const int tx = threadIdx.x, ty0 = threadIdx.y;
    const float invcnt = 1.f / (float)(B_*N_);
    int o = o0 + tx;
    float mean = g_sum[4*512 + o] * invcnt;
    float var  = g_ssq[4*512 + o] * invcnt - mean*mean;
    float a  = gm[o] * rsqrtf(var + 1e-5f);
    float c0 = bt[o] - mean*a;
    #pragma unroll
    for (int i = 0; i < 4; i++) {
        int ty = ty0 + i*8;
        float y = g_uv[((long)b*N_ + n0 + ty)*CB + o];
        tile[ty][tx] = tanhf(a*y + c0);
    }
    __syncthreads();
    #pragma unroll
    for (int i = 0; i < 4; i++) {
        int ty = ty0 + i*8;
        out[((long)b*CB + o0 + ty)*N_ + n0 + tx] = tile[tx][ty];
    }
}

// ---------------- launch ----------------
extern "C" void kernel_launch(void* const* d_in, const int* in_sizes, int n_in,
                              void* d_out, int out_size) {
    const float* x = (const float*)d_in[0];
    const float* W[5]; const float* G[5]; const float* Bt[5];
    for (int i = 0; i < 5; i++) {
        W[i]  = (const float*)d_in[1 + 3*i];
        G[i]  = (const float*)d_in[2 + 3*i];
        Bt[i] = (const float*)d_in[3 + 3*i];
    }
    float* out = (float*)d_out;

    float* xcn;   cudaGetSymbolAddress((void**)&xcn,  g_xcn);
    float* xnc;   cudaGetSymbolAddress((void**)&xnc,  g_xnc);
    float* x0nc;  cudaGetSymbolAddress((void**)&x0nc, g_x0nc);
    float* uv;    cudaGetSymbolAddress((void**)&uv,   g_uv);
    float4* wt;   cudaGetSymbolAddress((void**)&wt,   g_wT4);

    const int SMK3   = 4*TMK*4   + 2*4*TNK*8  + 2*TNK*8;   // 12288
    const int SMK64  = 64*TMK*4  + 2*16*TNK*8 + 2*TNK*8;   // 67584
    const int SMK128 = 128*TMK*4 + 2*16*TNK*8 + 2*TNK*8;   // 100352
    cudaFuncSetAttribute(k_knn<3>,   cudaFuncAttributeMaxDynamicSharedMemorySize, SMK3);
    cudaFuncSetAttribute(k_knn<64>,  cudaFuncAttributeMaxDynamicSharedMemorySize, SMK64);
    cudaFuncSetAttribute(k_knn<128>, cudaFuncAttributeMaxDynamicSharedMemorySize, SMK128);

    const float invE = 1.f / (float)(B_*N_*K_);
    const dim3 kg(N_/TMK, B_);
    const int wstart[5] = {0, 128, 2176, 6272, 22656};

    // stage 0 (ordered so launch idx 3 = k_knn<3> for the profiler slot)
    k_prep_w_all<<<(88192 + 255)/256, 256>>>(W[0], W[1], W[2], W[3], W[4]);
    k_prep_x0<<<(B_*N_ + 255)/256, 256>>>(x);
    k_gemm<64><<<dim3(128, 2), 256>>>(x0nc, 4, 0, 4, 1, wt + wstart[0], 128, uv);
    k_knn<3><<<kg, 256, SMK3>>>(x, (long)3*N_);
    k_edge_max<<<B_*N_/PP, 64>>>(uv, 64, 128, 0);
    k_fin_edge<<<B_*N_, 64>>>(64, 0, 0, G[0], Bt[0], invE);
    // stage 1: C=64 -> O=64
    k_knn<64><<<kg, 256, SMK64>>>(xcn, (long)CB*N_);
    k_gemm<64><<<dim3(128, 2), 256>>>(xnc, CB, 0, 64, 16, wt + wstart[1], 128, uv);
    k_edge_max<<<B_*N_/PP, 64>>>(uv, 64, 128, 1);
    k_fin_edge<<<B_*N_, 64>>>(64, 64, 1, G[1], Bt[1], invE);
    // stage 2: C=64 -> O=128
    k_knn<64><<<kg, 256, SMK64>>>(xcn + (long)64*N_, (long)CB*N_);
    k_gemm<128><<<dim3(128, 2), 256>>>(xnc, CB, 64, 64, 16, wt + wstart[2], 256, uv);
    k_edge_max<<<B_*N_/PP, 128>>>(uv, 128, 256, 2);
    k_fin_edge<<<B_*N_, 128>>>(128, 128, 2, G[2], Bt[2], invE);
    // stage 3: C=128 -> O=256
    k_knn<128><<<kg, 256, SMK128>>>(xcn + (long)128*N_, (long)CB*N_);
    k_gemm<128><<<dim3(128, 4), 256>>>(xnc, CB, 128, 128, 32, wt + wstart[3], 512, uv);
    k_edge_max<<<B_*N_/PP, 256>>>(uv, 256, 512, 3);
    k_fin_edge<<<B_*N_, 256>>>(256, 256, 3, G[3], Bt[3], invE);
    // block 5: 512x512
    k_gemm<128><<<dim3(128, 4), 256>>>(xnc, CB, 0, 512, 128, wt + wstart[4], 512, uv);
    k_stats5<<<128, 512>>>();
    k_fin5<<<dim3(N_/32, CB/32, B_), dim3(32, 8)>>>(G[4], Bt[4], out);
}

// round 7
// speedup vs baseline: 1.2198x; 1.2198x over previous
#include <cuda_runtime.h>
#include <math.h>

#define B_ 8
#define N_ 2048
#define K_ 4
#define CB 512
#define PP 8
#define TNK 128

typedef unsigned long long ull;

#define FFMA2(d,a,b) asm("fma.rn.f32x2 %0, %1, %2, %0;" : "+l"(d) : "l"(a), "l"(b))
__device__ __forceinline__ ull pack2(float lo, float hi) {
    ull r; asm("mov.b64 %0, {%1,%2};" : "=l"(r) : "f"(lo), "f"(hi)); return r;
}
__device__ __forceinline__ float2 unpack2(ull v) {
    float2 f; asm("mov.b64 {%0,%1}, %2;" : "=f"(f.x), "=f"(f.y) : "l"(v)); return f;
}

// top-4 insertion, strict > (stable: earlier-inserted wins ties)
__device__ __forceinline__ void ins4(float (&v)[4], int (&ix)[4], float p, int m) {
    if (p > v[3]) {
        if (p > v[1]) {
            if (p > v[0]) { v[3]=v[2];ix[3]=ix[2]; v[2]=v[1];ix[2]=ix[1]; v[1]=v[0];ix[1]=ix[0]; v[0]=p;ix[0]=m; }
            else          { v[3]=v[2];ix[3]=ix[2]; v[2]=v[1];ix[2]=ix[1]; v[1]=p;ix[1]=m; }
        } else {
            if (p > v[2]) { v[3]=v[2];ix[3]=ix[2]; v[2]=p;ix[2]=m; }
            else          { v[3]=p;ix[3]=m; }
        }
    }
}
__device__ __forceinline__ bool lexgt(float pv, int pi, float qv, int qi) {
    return (pv > qv) || (pv == qv && pi < qi);
}
__device__ __forceinline__ void ins4lex(float (&v)[4], int (&ix)[4], float p, int m) {
    if (lexgt(p, m, v[3], ix[3])) {
        if (lexgt(p, m, v[1], ix[1])) {
            if (lexgt(p, m, v[0], ix[0])) { v[3]=v[2];ix[3]=ix[2]; v[2]=v[1];ix[2]=ix[1]; v[1]=v[0];ix[1]=ix[0]; v[0]=p;ix[0]=m; }
            else                          { v[3]=v[2];ix[3]=ix[2]; v[2]=v[1];ix[2]=ix[1]; v[1]=p;ix[1]=m; }
        } else {
            if (lexgt(p, m, v[2], ix[2])) { v[3]=v[2];ix[3]=ix[2]; v[2]=p;ix[2]=m; }
            else                          { v[3]=p;ix[3]=m; }
        }
    }
}

// ---------------- scratch ----------------
__device__ float  g_xcn[(size_t)B_*CB*N_];   // [B][C][N]
__device__ float  g_xnc[(size_t)B_*N_*CB];   // [B][N][C]
__device__ float4 g_x0nc[(size_t)B_*N_];     // input [B][N][4], w = ||x||^2
__device__ float  g_xx[(size_t)B_*N_];
__device__ int4   g_idx4[(size_t)B_*N_];
__device__ float  g_uv[(size_t)B_*N_*512];
__device__ float  g_mx[(size_t)B_*N_*256];
__device__ float  g_mn[(size_t)B_*N_*256];
__device__ float  g_sum[5*512];
__device__ float  g_ssq[5*512];
__device__ float4 g_wT4[90112];

// ---------------- prep: pack weights + clear stats ----------------
__global__ void k_prep_w_all(const float* __restrict__ w1, const float* __restrict__ w2,
                             const float* __restrict__ w3, const float* __restrict__ w4,
                             const float* __restrict__ w5) {
    int t = blockIdx.x*blockDim.x + threadIdx.x;
    if (t < 5*512) { g_sum[t] = 0.f; g_ssq[t] = 0.f; }
    if (t >= 88192) return;
    const float* w; int realC, O, parts, lt;
    if      (t < 128)   { w = w1; realC = 3;   O = 64;  parts = 2; lt = t; }
    else if (t < 2176)  { w = w2; realC = 64;  O = 64;  parts = 2; lt = t - 128; }
    else if (t < 6272)  { w = w3; realC = 64;  O = 128; parts = 2; lt = t - 2176; }
    else if (t < 22656) { w = w4; realC = 128; O = 256; parts = 2; lt = t - 6272; }
    else                { w = w5; realC = 512; O = 512; parts = 1; lt = t - 22656; }
    int O2 = parts * O;
    int o2 = lt % O2; int c4 = lt / O2;
    int part = (o2 >= O) ? 1 : 0; int oc = o2 - part*O;
    float4 v; float* pv = (float*)&v;
    #pragma unroll
    for (int j = 0; j < 4; j++) {
        int c = c4*4 + j;
        pv[j] = (c < realC) ? w[oc*(parts*realC) + part*realC + c] : 0.f;
    }
    g_wT4[t] = v;
}

__global__ void k_prep_x0(const float* __restrict__ x) {
    int t = blockIdx.x*blockDim.x + threadIdx.x;
    if (t >= B_*N_) return;
    int b = t >> 11, n = t & (N_-1);
    float vx = x[(b*3+0)*N_ + n];
    float vy = x[(b*3+1)*N_ + n];
    float vz = x[(b*3+2)*N_ + n];
    float xx = fmaf(vz, vz, fmaf(vy, vy, vx*vx));
    g_x0nc[t] = make_float4(vx, vy, vz, xx);
    g_xx[t] = xx;
}

// ---------------- knn C=3: warp-per-row over resident point cloud ----------------
__global__ void __launch_bounds__(256) k_knn3w() {
    __shared__ float4 pts[N_];               // 32KB: (x,y,z,xx)
    const int b  = blockIdx.y;
    const int n0 = blockIdx.x * 32;
    const int tid = threadIdx.x;
    const int wid = tid >> 5, lane = tid & 31;
    for (int t = tid; t < N_; t += 256) pts[t] = g_x0nc[b*N_ + t];
    __syncthreads();
    #pragma unroll
    for (int r = 0; r < 4; r++) {
        const int n = n0 + wid*4 + r;
        float4 P = pts[n];
        float nxr = -P.w;
        float cv[4] = {-3.4e38f,-3.4e38f,-3.4e38f,-3.4e38f};
        int   ci[4] = {0,0,0,0};
        #pragma unroll 8
        for (int i = 0; i < 64; i++) {
            int m = i*32 + lane;
            float4 Q = pts[m];
            float acc = fmaf(P.z, Q.z, fmaf(P.y, Q.y, P.x*Q.x));
            float p = fmaf(2.f, acc, nxr) - Q.w;
            ins4(cv, ci, p, m);
        }
        #pragma unroll
        for (int st = 1; st <= 16; st <<= 1) {
            float pv[4]; int pi[4];
            #pragma unroll
            for (int q = 0; q < 4; q++) {
                pv[q] = __shfl_xor_sync(0xffffffffu, cv[q], st);
                pi[q] = __shfl_xor_sync(0xffffffffu, ci[q], st);
            }
            #pragma unroll
            for (int q = 0; q < 4; q++) ins4lex(cv, ci, pv[q], pi[q]);
        }
        if (lane == 0)
            g_idx4[b*N_ + n] = make_int4(ci[0], ci[1], ci[2], ci[3]);
    }
}

// ---------------- knn C=64/128: natural-B tiles, packed-column accumulators ----------------
template<int C>
__global__ void __launch_bounds__(128) k_knn(const float* __restrict__ base, long bstride) {
    constexpr int KCc = 16;
    constexpr int NCH = C / KCc;             // 4 or 8
    constexpr int TM  = 64;
    constexpr int NG  = (N_/TNK)*NCH;
    extern __shared__ char smraw[];
    float* Ash = (float*)smraw;                                   // [C][TM] natural
    float* Bsh = (float*)(smraw + (size_t)C*TM*4);                // [2][KCc][TNK] natural
    float* xxs = (float*)(smraw + (size_t)C*TM*4 + 2*KCc*TNK*4);  // [2][TNK]
    const int b  = blockIdx.y;
    const int n0 = blockIdx.x * TM;
    const float* X = base + (long)b*bstride;
    const float* xxg = g_xx + b*N_;
    const int tid = threadIdx.x;
    const int ty = tid >> 3, tx = tid & 7;   // 16 row-groups x 8 col-lanes
    const int r0 = ty*4;
    const int c0 = 2*tx;

    for (int t = tid; t < C*TM; t += 128) {
        int c = t >> 6, r = t & 63;
        Ash[t] = X[(long)c*N_ + n0 + r];
    }
    float xxr[4];
    #pragma unroll
    for (int i = 0; i < 4; i++) xxr[i] = xxg[n0 + r0 + i];

    float cv[4][4]; int ci[4][4];
    #pragma unroll
    for (int r = 0; r < 4; r++)
        #pragma unroll
        for (int q = 0; q < 4; q++) { cv[r][q] = -3.4e38f; ci[r][q] = 0; }

    // initial B chunk (mb=0, ch=0)
    for (int t = tid; t < KCc*TNK; t += 128) {
        int c = t >> 7, m = t & 127;
        Bsh[t] = X[(long)c*N_ + m];
    }
    xxs[tid] = xxg[tid];   // 128 threads == TNK
    __syncthreads();

    ull acc[4][8];
    #pragma unroll
    for (int i = 0; i < 4; i++)
        #pragma unroll
        for (int k = 0; k < 8; k++) acc[i][k] = 0ull;

    for (int g = 0; g < NG; g++) {
        const int mb = g / NCH, ch = g - mb*NCH;
        if (g + 1 < NG) {
            const int g1 = g + 1;
            const int mb1 = g1 / NCH, ch1 = g1 - mb1*NCH;
            const int m01 = mb1*TNK;
            float* bd = Bsh + (g1 & 1)*(KCc*TNK);
            #pragma unroll
            for (int t = tid; t < KCc*TNK; t += 128) {
                int c = t >> 7, m = t & 127;
                bd[t] = X[(long)(ch1*KCc + c)*N_ + m01 + m];
            }
            if (ch1 == 0) xxs[(mb1 & 1)*TNK + tid] = xxg[m01 + tid];
        }
        const float* bb = Bsh + (g & 1)*(KCc*TNK);
        #pragma unroll
        for (int cc = 0; cc < KCc; cc++) {
            float4 a4 = *(const float4*)&Ash[(ch*KCc + cc)*TM + r0];
            ull ad0 = pack2(a4.x, a4.x);
            ull ad1 = pack2(a4.y, a4.y);
            ull ad2 = pack2(a4.z, a4.z);
            ull ad3 = pack2(a4.w, a4.w);
            const ull* bp = (const ull*)&bb[cc*TNK];
            #pragma unroll
            for (int k = 0; k < 8; k++) {
                ull bpair = bp[k*8 + tx];        // cols 16k+2tx, 16k+2tx+1
                FFMA2(acc[0][k], ad0, bpair);
                FFMA2(acc[1][k], ad1, bpair);
                FFMA2(acc[2][k], ad2, bpair);
                FFMA2(acc[3][k], ad3, bpair);
            }
        }
        if (ch == NCH - 1) {
            const float* xxb = xxs + (mb & 1)*TNK;
            const int m0 = mb*TNK;
            #pragma unroll
            for (int k = 0; k < 8; k++) {
                const int col = m0 + 16*k + c0;
                float xc0 = xxb[16*k + c0];
                float xc1 = xxb[16*k + c0 + 1];
                #pragma unroll
                for (int i = 0; i < 4; i++) {
                    float2 u = unpack2(acc[i][k]);
                    ins4(cv[i], ci[i], fmaf(2.f, u.x, -xxr[i]) - xc0, col);
                    ins4(cv[i], ci[i], fmaf(2.f, u.y, -xxr[i]) - xc1, col + 1);
                    acc[i][k] = 0ull;
                }
            }
        }
        __syncthreads();
    }
    // butterfly merge across the 8 column-lanes (lex: order-independent)
    #pragma unroll
    for (int st = 1; st <= 4; st <<= 1) {
        #pragma unroll
        for (int r = 0; r < 4; r++) {
            float pv[4]; int pi[4];
            #pragma unroll
            for (int q = 0; q < 4; q++) {
                pv[q] = __shfl_xor_sync(0xffffffffu, cv[r][q], st);
                pi[q] = __shfl_xor_sync(0xffffffffu, ci[r][q], st);
            }
            #pragma unroll
            for (int q = 0; q < 4; q++) ins4lex(cv[r], ci[r], pv[q], pi[q]);
        }
    }
    if (tx == 0) {
        #pragma unroll
        for (int r = 0; r < 4; r++)
            g_idx4[b*N_ + n0 + r0 + r] = make_int4(ci[r][0], ci[r][1], ci[r][2], ci[r][3]);
    }
}

// ---------------- generic GEMM: out[pt][O2] = src[pt][C] * W[C][O2] ----------------
template<int TN>
__global__ void __launch_bounds__(256) k_gemm(const float* __restrict__ src, int CS, int coff,
                                              int C, int c4n, const float4* __restrict__ wb,
                                              int O2, float* __restrict__ out) {
    constexpr int CT = TN/16;
    __shared__ float Ash[16*132];
    __shared__ ull   Bsh[16*TN];
    const int pt0 = blockIdx.x * 128;
    const int ob0 = blockIdx.y * TN;
    const int tid = threadIdx.x;
    const int ty = tid >> 4, tx = tid & 15;
    const int r0 = ty*8;

    ull acc[4][CT];
    #pragma unroll
    for (int p = 0; p < 4; p++)
        #pragma unroll
        for (int j = 0; j < CT; j++) acc[p][j] = 0ull;

    const int C16 = (C + 15) & ~15;
    for (int kc = 0; kc < C16; kc += 16) {
        #pragma unroll
        for (int t = tid; t < 16*128; t += 256) {
            int c = t & 15, r = t >> 4;
            float v = (kc + c < C) ? src[(long)(pt0 + r)*CS + coff + kc + c] : 0.f;
            Ash[c*132 + r] = v;
        }
        #pragma unroll
        for (int t = tid; t < 4*TN; t += 256) {
            int q = t / TN, o = t - q*TN;
            int c4 = (kc >> 2) + q;
            float4 w = (c4 < c4n) ? wb[(long)c4*O2 + ob0 + o] : make_float4(0.f,0.f,0.f,0.f);
            Bsh[(4*q+0)*TN + o] = pack2(w.x, w.x);
            Bsh[(4*q+1)*TN + o] = pack2(w.y, w.y);
            Bsh[(4*q+2)*TN + o] = pack2(w.z, w.z);
            Bsh[(4*q+3)*TN + o] = pack2(w.w, w.w);
        }
        __syncthreads();
        #pragma unroll
        for (int cc = 0; cc < 16; cc++) {
            ulonglong2 aA = *(const ulonglong2*)&Ash[cc*132 + r0];
            ulonglong2 aB = *(const ulonglong2*)&Ash[cc*132 + r0 + 4];
            const ull* bp = &Bsh[cc*TN + tx];
            #pragma unroll
            for (int j = 0; j < CT; j++) {
                ull bb = bp[j*16];
                FFMA2(acc[0][j], aA.x, bb);
                FFMA2(acc[1][j], aA.y, bb);
                FFMA2(acc[2][j], aB.x, bb);
                FFMA2(acc[3][j], aB.y, bb);
            }
        }
        __syncthreads();
    }
    #pragma unroll
    for (int p = 0; p < 4; p++) {
        long rowL = (long)(pt0 + r0 + 2*p) * O2 + ob0 + tx;
        #pragma unroll
        for (int j = 0; j < CT; j++) {
            float2 u = unpack2(acc[p][j]);
            out[rowL + j*16]      = u.x;
            out[rowL + O2 + j*16] = u.y;
        }
    }
}

// ---------------- gather + minmax over k + stats ----------------
__global__ void k_edge_max(const float* __restrict__ uv, int O, int O2, int stage) {
    __shared__ int sidx[PP*K_];
    const int blk = blockIdx.x;
    const int pt0 = blk * PP;
    const int o = threadIdx.x;
    const int b = pt0 >> 11;
    if (o < PP) ((int4*)sidx)[o] = g_idx4[pt0 + o];
    __syncthreads();
    float s1 = 0.f, s2 = 0.f;
    #pragma unroll
    for (int p = 0; p < PP; p++) {
        float v = uv[(long)(pt0 + p)*O2 + O + o];
        float mx = -3.4e38f, mn = 3.4e38f;
        #pragma unroll
        for (int k = 0; k < K_; k++) {
            int nb = sidx[p*K_ + k];
            float u = uv[(long)(b*N_ + nb)*O2 + o];
            float y = u + v;
            mx = fmaxf(mx, y); mn = fminf(mn, y);
            s1 += y; s2 += y*y;
        }
        g_mx[(long)(pt0 + p)*O + o] = mx;
        g_mn[(long)(pt0 + p)*O + o] = mn;
    }
    atomicAdd(&g_sum[stage*512 + o], s1);
    atomicAdd(&g_ssq[stage*512 + o], s2);
}

// ---------------- BN finalize + relu + both layouts + next-stage norms ----------------
__global__ void k_fin_edge(int O, int coff, int stage, const float* __restrict__ gm,
                           const float* __restrict__ bt, float invcnt) {
    __shared__ float wsum[8];
    const int bn = blockIdx.x;
    const int o  = threadIdx.x;
    const int so = stage*512 + o;
    float mean = g_sum[so] * invcnt;
    float var  = g_ssq[so] * invcnt - mean*mean;
    float a  = gm[o] * rsqrtf(var + 1e-5f);
    float c0 = bt[o] - mean*a;
    long t = (long)bn*O + o;
    float z = (a >= 0.f) ? (a*g_mx[t] + c0) : (a*g_mn[t] + c0);
    z = fmaxf(z, 0.f);
    int b = bn >> 11, n = bn & (N_-1);
    g_xnc[(long)bn*CB + coff + o] = z;
    g_xcn[((long)b*CB + coff + o)*N_ + n] = z;
    float r = z*z;
    #pragma unroll
    for (int d = 16; d; d >>= 1) r += __shfl_xor_sync(0xffffffffu, r, d);
    if ((o & 31) == 0) wsum[o >> 5] = r;
    __syncthreads();
    if (o == 0) {
        float s = 0.f;
        #pragma unroll
        for (int w = 0; w < 8; w++) if (w < (O >> 5)) s += wsum[w];
        g_xx[bn] = s;
    }
}

// ---------------- conv5 stats ----------------
__global__ void __launch_bounds__(512) k_stats5() {
    const int o = threadIdx.x;
    const int p0 = blockIdx.x * 128;
    float s1 = 0.f, s2 = 0.f;
    for (int i = 0; i < 128; i++) {
        float y = g_uv[(long)(p0 + i)*CB + o];
        s1 += y; s2 += y*y;
    }
    atomicAdd(&g_sum[4*512 + o], s1);
    atomicAdd(&g_ssq[4*512 + o], s2);
}

__global__ void k_fin5(const float* __restrict__ gm, const float* __restrict__ bt,
                       float* __restrict__ out) {
    __shared__ float tile[32][33];
    const int b  = blockIdx.z;
    const int o0 = blockIdx.y*32;
    const int n0 = blockIdx.x*32;
    const int tx = threadIdx.x, ty0 = threadIdx.y;
    const float invcnt = 1.f / (float)(B_*N_);
    int o = o0 + tx;
    float mean = g_sum[4*512 + o] * invcnt;
    float var  = g_ssq[4*512 + o] * invcnt - mean*mean;
    float a  = gm[o] * rsqrtf(var + 1e-5f);
    float c0 = bt[o] - mean*a;
    #pragma unroll
    for (int i = 0; i < 4; i++) {
        int ty = ty0 + i*8;
        float y = g_uv[((long)b*N_ + n0 + ty)*CB + o];
        tile[ty][tx] = tanhf(a*y + c0);
    }
    __syncthreads();
    #pragma unroll
    for (int i = 0; i < 4; i++) {
        int ty = ty0 + i*8;
        out[((long)b*CB + o0 + ty)*N_ + n0 + tx] = tile[tx][ty];
    }
}

// ---------------- launch ----------------
extern "C" void kernel_launch(void* const* d_in, const int* in_sizes, int n_in,
                              void* d_out, int out_size) {
    const float* x = (const float*)d_in[0];
    const float* W[5]; const float* G[5]; const float* Bt[5];
    for (int i = 0; i < 5; i++) {
        W[i]  = (const float*)d_in[1 + 3*i];
        G[i]  = (const float*)d_in[2 + 3*i];
        Bt[i] = (const float*)d_in[3 + 3*i];
    }
    float* out = (float*)d_out;

    float* xcn;   cudaGetSymbolAddress((void**)&xcn,  g_xcn);
    float* xnc;   cudaGetSymbolAddress((void**)&xnc,  g_xnc);
    float* x0nc;  cudaGetSymbolAddress((void**)&x0nc, g_x0nc);
    float* uv;    cudaGetSymbolAddress((void**)&uv,   g_uv);
    float4* wt;   cudaGetSymbolAddress((void**)&wt,   g_wT4);

    const int SMK64  = 64*64*4  + 2*16*TNK*4 + 2*TNK*4;   // 33792
    const int SMK128 = 128*64*4 + 2*16*TNK*4 + 2*TNK*4;   // 50176
    cudaFuncSetAttribute(k_knn<64>,  cudaFuncAttributeMaxDynamicSharedMemorySize, SMK64);
    cudaFuncSetAttribute(k_knn<128>, cudaFuncAttributeMaxDynamicSharedMemorySize, SMK128);

    const float invE = 1.f / (float)(B_*N_*K_);
    const dim3 kg(N_/64, B_);
    const int wstart[5] = {0, 128, 2176, 6272, 22656};

    // stage 0 (launch idx 3 = k_knn3w for the profiler slot)
    k_prep_w_all<<<(88192 + 255)/256, 256>>>(W[0], W[1], W[2], W[3], W[4]);
    k_prep_x0<<<(B_*N_ + 255)/256, 256>>>(x);
    k_gemm<64><<<dim3(128, 2), 256>>>(x0nc, 4, 0, 4, 1, wt + wstart[0], 128, uv);
    k_knn3w<<<dim3(N_/32, B_), 256>>>();
    k_edge_max<<<B_*N_/PP, 64>>>(uv, 64, 128, 0);
    k_fin_edge<<<B_*N_, 64>>>(64, 0, 0, G[0], Bt[0], invE);
    // stage 1: C=64 -> O=64
    k_knn<64><<<kg, 128, SMK64>>>(xcn, (long)CB*N_);
    k_gemm<64><<<dim3(128, 2), 256>>>(xnc, CB, 0, 64, 16, wt + wstart[1], 128, uv);
    k_edge_max<<<B_*N_/PP, 64>>>(uv, 64, 128, 1);
    k_fin_edge<<<B_*N_, 64>>>(64, 64, 1, G[1], Bt[1], invE);
    // stage 2: C=64 -> O=128
    k_knn<64><<<kg, 128, SMK64>>>(xcn + (long)64*N_, (long)CB*N_);
    k_gemm<128><<<dim3(128, 2), 256>>>(xnc, CB, 64, 64, 16, wt + wstart[2], 256, uv);
    k_edge_max<<<B_*N_/PP, 128>>>(uv, 128, 256, 2);
    k_fin_edge<<<B_*N_, 128>>>(128, 128, 2, G[2], Bt[2], invE);
    // stage 3: C=128 -> O=256
    k_knn<128><<<kg, 128, SMK128>>>(xcn + (long)128*N_, (long)CB*N_);
    k_gemm<128><<<dim3(128, 4), 256>>>(xnc, CB, 128, 128, 32, wt + wstart[3], 512, uv);
    k_edge_max<<<B_*N_/PP, 256>>>(uv, 256, 512, 3);
    k_fin_edge<<<B_*N_, 256>>>(256, 256, 3, G[3], Bt[3], invE);
    // block 5: 512x512
    k_gemm<128><<<dim3(128, 4), 256>>>(xnc, CB, 0, 512, 128, wt + wstart[4], 512, uv);
    k_stats5<<<128, 512>>>();
    k_fin5<<<dim3(N_/32, CB/32, B_), dim3(32, 8)>>>(G[4], Bt[4], out);
}

// round 8
// speedup vs baseline: 1.2275x; 1.0063x over previous
#include <cuda_runtime.h>
#include <math.h>

#define B_ 8
#define N_ 2048
#define K_ 4
#define CB 512
#define PP 8
#define TNK 128

typedef unsigned long long ull;

#define FFMA2(d,a,b) asm("fma.rn.f32x2 %0, %1, %2, %0;" : "+l"(d) : "l"(a), "l"(b))
#define ADD2(d,a,b)  asm("add.rn.f32x2 %0, %1, %2;" : "=l"(d) : "l"(a), "l"(b))
__device__ __forceinline__ ull pack2(float lo, float hi) {
    ull r; asm("mov.b64 %0, {%1,%2};" : "=l"(r) : "f"(lo), "f"(hi)); return r;
}
__device__ __forceinline__ float2 unpack2(ull v) {
    float2 f; asm("mov.b64 {%0,%1}, %2;" : "=f"(f.x), "=f"(f.y) : "l"(v)); return f;
}

// branchless top-4 insert, strict > (stable: earlier-inserted wins ties)
__device__ __forceinline__ void ins4b(float (&v)[4], int (&ix)[4], float p, int m) {
    float t = p; int ti = m;
    #pragma unroll
    for (int q = 0; q < 4; q++) {
        bool c = t > v[q];
        float vq = v[q]; int iq = ix[q];
        v[q]  = c ? t  : vq;  ix[q] = c ? ti : iq;
        t     = c ? vq : t;   ti    = c ? iq : ti;
    }
}
// branchless lexicographic (val desc, idx asc) — order-independent merge
__device__ __forceinline__ void ins4lexb(float (&v)[4], int (&ix)[4], float p, int m) {
    float t = p; int ti = m;
    #pragma unroll
    for (int q = 0; q < 4; q++) {
        bool c = (t > v[q]) || (t == v[q] && ti < ix[q]);
        float vq = v[q]; int iq = ix[q];
        v[q]  = c ? t  : vq;  ix[q] = c ? ti : iq;
        t     = c ? vq : t;   ti    = c ? iq : ti;
    }
}

// ---------------- scratch ----------------
__device__ float  g_xcn[(size_t)B_*CB*N_];   // [B][C][N]
__device__ float  g_xnc[(size_t)B_*N_*CB];   // [B][N][C]
__device__ float4 g_x0nc[(size_t)B_*N_];     // input [B][N][4], w = ||x||^2
__device__ float  g_xx[(size_t)B_*N_];
__device__ int4   g_idx4[(size_t)B_*N_];
__device__ float  g_uv[(size_t)B_*N_*512];
__device__ float  g_mx[(size_t)B_*N_*256];
__device__ float  g_mn[(size_t)B_*N_*256];
__device__ float  g_sum[5*512];
__device__ float  g_ssq[5*512];
__device__ float4 g_wT4[90112];

// ---------------- prep: pack weights + clear stats ----------------
__global__ void k_prep_w_all(const float* __restrict__ w1, const float* __restrict__ w2,
                             const float* __restrict__ w3, const float* __restrict__ w4,
                             const float* __restrict__ w5) {
    int t = blockIdx.x*blockDim.x + threadIdx.x;
    if (t < 5*512) { g_sum[t] = 0.f; g_ssq[t] = 0.f; }
    if (t >= 88192) return;
    const float* w; int realC, O, parts, lt;
    if      (t < 128)   { w = w1; realC = 3;   O = 64;  parts = 2; lt = t; }
    else if (t < 2176)  { w = w2; realC = 64;  O = 64;  parts = 2; lt = t - 128; }
    else if (t < 6272)  { w = w3; realC = 64;  O = 128; parts = 2; lt = t - 2176; }
    else if (t < 22656) { w = w4; realC = 128; O = 256; parts = 2; lt = t - 6272; }
    else                { w = w5; realC = 512; O = 512; parts = 1; lt = t - 22656; }
    int O2 = parts * O;
    int o2 = lt % O2; int c4 = lt / O2;
    int part = (o2 >= O) ? 1 : 0; int oc = o2 - part*O;
    float4 v; float* pv = (float*)&v;
    #pragma unroll
    for (int j = 0; j < 4; j++) {
        int c = c4*4 + j;
        pv[j] = (c < realC) ? w[oc*(parts*realC) + part*realC + c] : 0.f;
    }
    g_wT4[t] = v;
}

__global__ void k_prep_x0(const float* __restrict__ x) {
    int t = blockIdx.x*blockDim.x + threadIdx.x;
    if (t >= B_*N_) return;
    int b = t >> 11, n = t & (N_-1);
    float vx = x[(b*3+0)*N_ + n];
    float vy = x[(b*3+1)*N_ + n];
    float vz = x[(b*3+2)*N_ + n];
    float xx = fmaf(vz, vz, fmaf(vy, vy, vx*vx));
    g_x0nc[t] = make_float4(vx, vy, vz, xx);
    g_xx[t] = xx;
}

// ---------------- knn C=3: warp-per-4-rows, shared Q, packed pd, branchless ----------------
__global__ void __launch_bounds__(256) k_knn3w() {
    __shared__ float4 pts[N_];               // 32KB: (x,y,z,xx)
    const int b  = blockIdx.y;
    const int n0 = blockIdx.x * 32;
    const int tid = threadIdx.x;
    const int wid = tid >> 5, lane = tid & 31;
    for (int t = tid; t < N_; t += 256) pts[t] = g_x0nc[b*N_ + t];
    __syncthreads();

    const int n = n0 + wid*4;
    float4 P0 = pts[n], P1 = pts[n+1], P2 = pts[n+2], P3 = pts[n+3];
    const ull p01x = pack2(P0.x, P1.x), p23x = pack2(P2.x, P3.x);
    const ull p01y = pack2(P0.y, P1.y), p23y = pack2(P2.y, P3.y);
    const ull p01z = pack2(P0.z, P1.z), p23z = pack2(P2.z, P3.z);
    const ull nr01 = pack2(-P0.w, -P1.w), nr23 = pack2(-P2.w, -P3.w);
    const ull two2 = pack2(2.f, 2.f);

    float cv[4][4]; int ci[4][4];
    #pragma unroll
    for (int r = 0; r < 4; r++)
        #pragma unroll
        for (int q = 0; q < 4; q++) { cv[r][q] = -3.4e38f; ci[r][q] = 0; }

    #pragma unroll 4
    for (int i = 0; i < 64; i++) {
        const int m = i*32 + lane;
        float4 Q = pts[m];
        ull qx = pack2(Q.x, Q.x), qy = pack2(Q.y, Q.y), qz = pack2(Q.z, Q.z);
        ull nqw = pack2(-Q.w, -Q.w);
        ull a01 = 0ull, a23 = 0ull;
        FFMA2(a01, p01x, qx); FFMA2(a01, p01y, qy); FFMA2(a01, p01z, qz);
        FFMA2(a23, p23x, qx); FFMA2(a23, p23y, qy); FFMA2(a23, p23z, qz);
        ull t01 = nr01; FFMA2(t01, a01, two2);
        ull t23 = nr23; FFMA2(t23, a23, two2);
        ull pd01; ADD2(pd01, t01, nqw);
        ull pd23; ADD2(pd23, t23, nqw);
        float2 u01 = unpack2(pd01), u23 = unpack2(pd23);
        ins4b(cv[0], ci[0], u01.x, m);
        ins4b(cv[1], ci[1], u01.y, m);
        ins4b(cv[2], ci[2], u23.x, m);
        ins4b(cv[3], ci[3], u23.y, m);
    }
    #pragma unroll
    for (int st = 1; st <= 16; st <<= 1) {
        #pragma unroll
        for (int r = 0; r < 4; r++) {
            float pv[4]; int pi[4];
            #pragma unroll
            for (int q = 0; q < 4; q++) {
                pv[q] = __shfl_xor_sync(0xffffffffu, cv[r][q], st);
                pi[q] = __shfl_xor_sync(0xffffffffu, ci[r][q], st);
            }
            #pragma unroll
            for (int q = 0; q < 4; q++) ins4lexb(cv[r], ci[r], pv[q], pi[q]);
        }
    }
    if (lane == 0) {
        #pragma unroll
        for (int r = 0; r < 4; r++)
            g_idx4[b*N_ + n + r] = make_int4(ci[r][0], ci[r][1], ci[r][2], ci[r][3]);
    }
}

// ---------------- knn C=64/128: natural-B tiles, rowmax-guarded scan ----------------
template<int C>
__global__ void __launch_bounds__(128) k_knn(const float* __restrict__ base, long bstride) {
    constexpr int KCc = 16;
    constexpr int NCH = C / KCc;
    constexpr int TM  = 64;
    constexpr int NG  = (N_/TNK)*NCH;
    extern __shared__ char smraw[];
    float* Ash = (float*)smraw;                                   // [C][TM]
    float* Bsh = (float*)(smraw + (size_t)C*TM*4);                // [2][KCc][TNK]
    float* xxs = (float*)(smraw + (size_t)C*TM*4 + 2*KCc*TNK*4);  // [2][TNK]
    const int b  = blockIdx.y;
    const int n0 = blockIdx.x * TM;
    const float* X = base + (long)b*bstride;
    const float* xxg = g_xx + b*N_;
    const int tid = threadIdx.x;
    const int ty = tid >> 3, tx = tid & 7;
    const int r0 = ty*4;
    const int c0 = 2*tx;

    for (int t = tid; t < C*TM; t += 128) {
        int c = t >> 6, r = t & 63;
        Ash[t] = X[(long)c*N_ + n0 + r];
    }
    float xxr[4];
    #pragma unroll
    for (int i = 0; i < 4; i++) xxr[i] = xxg[n0 + r0 + i];

    float cv[4][4]; int ci[4][4];
    #pragma unroll
    for (int r = 0; r < 4; r++)
        #pragma unroll
        for (int q = 0; q < 4; q++) { cv[r][q] = -3.4e38f; ci[r][q] = 0; }

    for (int t = tid; t < KCc*TNK; t += 128) {
        int c = t >> 7, m = t & 127;
        Bsh[t] = X[(long)c*N_ + m];
    }
    xxs[tid] = xxg[tid];
    __syncthreads();

    ull acc[4][8];
    #pragma unroll
    for (int i = 0; i < 4; i++)
        #pragma unroll
        for (int k = 0; k < 8; k++) acc[i][k] = 0ull;

    for (int g = 0; g < NG; g++) {
        const int mb = g / NCH, ch = g - mb*NCH;
        if (g + 1 < NG) {
            const int g1 = g + 1;
            const int mb1 = g1 / NCH, ch1 = g1 - mb1*NCH;
            const int m01 = mb1*TNK;
            float* bd = Bsh + (g1 & 1)*(KCc*TNK);
            #pragma unroll
            for (int t = tid; t < KCc*TNK; t += 128) {
                int c = t >> 7, m = t & 127;
                bd[t] = X[(long)(ch1*KCc + c)*N_ + m01 + m];
            }
            if (ch1 == 0) xxs[(mb1 & 1)*TNK + tid] = xxg[m01 + tid];
        }
        const float* bb = Bsh + (g & 1)*(KCc*TNK);
        #pragma unroll
        for (int cc = 0; cc < KCc; cc++) {
            float4 a4 = *(const float4*)&Ash[(ch*KCc + cc)*TM + r0];
            ull ad0 = pack2(a4.x, a4.x);
            ull ad1 = pack2(a4.y, a4.y);
            ull ad2 = pack2(a4.z, a4.z);
            ull ad3 = pack2(a4.w, a4.w);
            const ull* bp = (const ull*)&bb[cc*TNK];
            #pragma unroll
            for (int k = 0; k < 8; k++) {
                ull bpair = bp[k*8 + tx];
                FFMA2(acc[0][k], ad0, bpair);
                FFMA2(acc[1][k], ad1, bpair);
                FFMA2(acc[2][k], ad2, bpair);
                FFMA2(acc[3][k], ad3, bpair);
            }
        }
        if (ch == NCH - 1) {
            const float* xxb = xxs + (mb & 1)*TNK;
            const int m0 = mb*TNK;
            float xcl[16];
            #pragma unroll
            for (int k = 0; k < 8; k++) {
                float2 x2 = *(const float2*)&xxb[16*k + c0];
                xcl[2*k] = x2.x; xcl[2*k+1] = x2.y;
            }
            #pragma unroll
            for (int i = 0; i < 4; i++) {
                float pd[16];
                float rmax = -3.4e38f;
                #pragma unroll
                for (int k = 0; k < 8; k++) {
                    float2 u = unpack2(acc[i][k]);
                    float p0 = fmaf(2.f, u.x, -xxr[i]) - xcl[2*k];
                    float p1 = fmaf(2.f, u.y, -xxr[i]) - xcl[2*k+1];
                    pd[2*k] = p0; pd[2*k+1] = p1;
                    rmax = fmaxf(rmax, fmaxf(p0, p1));
                    acc[i][k] = 0ull;
                }
                if (rmax > cv[i][3]) {
                    #pragma unroll
                    for (int k = 0; k < 16; k++)
                        ins4b(cv[i], ci[i], pd[k], m0 + 16*(k >> 1) + c0 + (k & 1));
                }
            }
        }
        __syncthreads();
    }
    #pragma unroll
    for (int st = 1; st <= 4; st <<= 1) {
        #pragma unroll
        for (int r = 0; r < 4; r++) {
            float pv[4]; int pi[4];
            #pragma unroll
            for (int q = 0; q < 4; q++) {
                pv[q] = __shfl_xor_sync(0xffffffffu, cv[r][q], st);
                pi[q] = __shfl_xor_sync(0xffffffffu, ci[r][q], st);
            }
            #pragma unroll
            for (int q = 0; q < 4; q++) ins4lexb(cv[r], ci[r], pv[q], pi[q]);
        }
    }
    if (tx == 0) {
        #pragma unroll
        for (int r = 0; r < 4; r++)
            g_idx4[b*N_ + n0 + r0 + r] = make_int4(ci[r][0], ci[r][1], ci[r][2], ci[r][3]);
    }
}

// ---------------- generic GEMM: out[pt][O2] = src[pt][C] * W[C][O2] ----------------
template<int TN>
__global__ void __launch_bounds__(256) k_gemm(const float* __restrict__ src, int CS, int coff,
                                              int C, int c4n, const float4* __restrict__ wb,
                                              int O2, float* __restrict__ out) {
    constexpr int CT = TN/16;
    __shared__ float Ash[16*132];
    __shared__ ull   Bsh[16*TN];
    const int pt0 = blockIdx.x * 128;
    const int ob0 = blockIdx.y * TN;
    const int tid = threadIdx.x;
    const int ty = tid >> 4, tx = tid & 15;
    const int r0 = ty*8;

    ull acc[4][CT];
    #pragma unroll
    for (int p = 0; p < 4; p++)
        #pragma unroll
        for (int j = 0; j < CT; j++) acc[p][j] = 0ull;

    const int C16 = (C + 15) & ~15;
    for (int kc = 0; kc < C16; kc += 16) {
        #pragma unroll
        for (int t = tid; t < 16*128; t += 256) {
            int c = t & 15, r = t >> 4;
            float v = (kc + c < C) ? src[(long)(pt0 + r)*CS + coff + kc + c] : 0.f;
            Ash[c*132 + r] = v;
        }
        #pragma unroll
        for (int t = tid; t < 4*TN; t += 256) {
            int q = t / TN, o = t - q*TN;
            int c4 = (kc >> 2) + q;
            float4 w = (c4 < c4n) ? wb[(long)c4*O2 + ob0 + o] : make_float4(0.f,0.f,0.f,0.f);
            Bsh[(4*q+0)*TN + o] = pack2(w.x, w.x);
            Bsh[(4*q+1)*TN + o] = pack2(w.y, w.y);
            Bsh[(4*q+2)*TN + o] = pack2(w.z, w.z);
            Bsh[(4*q+3)*TN + o] = pack2(w.w, w.w);
        }
        __syncthreads();
        #pragma unroll
        for (int cc = 0; cc < 16; cc++) {
            ulonglong2 aA = *(const ulonglong2*)&Ash[cc*132 + r0];
            ulonglong2 aB = *(const ulonglong2*)&Ash[cc*132 + r0 + 4];
            const ull* bp = &Bsh[cc*TN + tx];
            #pragma unroll
            for (int j = 0; j < CT; j++) {
                ull bb = bp[j*16];
                FFMA2(acc[0][j], aA.x, bb);
                FFMA2(acc[1][j], aA.y, bb);
                FFMA2(acc[2][j], aB.x, bb);
                FFMA2(acc[3][j], aB.y, bb);
            }
        }
        __syncthreads();
    }
    #pragma unroll
    for (int p = 0; p < 4; p++) {
        long rowL = (long)(pt0 + r0 + 2*p) * O2 + ob0 + tx;
        #pragma unroll
        for (int j = 0; j < CT; j++) {
            float2 u = unpack2(acc[p][j]);
            out[rowL + j*16]      = u.x;
            out[rowL + O2 + j*16] = u.y;
        }
    }
}

// ---------------- gather + minmax over k + stats ----------------
__global__ void k_edge_max(const float* __restrict__ uv, int O, int O2, int stage) {
    __shared__ int sidx[PP*K_];
    const int blk = blockIdx.x;
    const int pt0 = blk * PP;
    const int o = threadIdx.x;
    const int b = pt0 >> 11;
    if (o < PP) ((int4*)sidx)[o] = g_idx4[pt0 + o];
    __syncthreads();
    float s1 = 0.f, s2 = 0.f;
    #pragma unroll
    for (int p = 0; p < PP; p++) {
        float v = uv[(long)(pt0 + p)*O2 + O + o];
        float mx = -3.4e38f, mn = 3.4e38f;
        #pragma unroll
        for (int k = 0; k < K_; k++) {
            int nb = sidx[p*K_ + k];
            float u = uv[(long)(b*N_ + nb)*O2 + o];
            float y = u + v;
            mx = fmaxf(mx, y); mn = fminf(mn, y);
            s1 += y; s2 += y*y;
        }
        g_mx[(long)(pt0 + p)*O + o] = mx;
        g_mn[(long)(pt0 + p)*O + o] = mn;
    }
    atomicAdd(&g_sum[stage*512 + o], s1);
    atomicAdd(&g_ssq[stage*512 + o], s2);
}

// ---------------- BN finalize + relu + both layouts + next-stage norms ----------------
__global__ void k_fin_edge(int O, int coff, int stage, const float* __restrict__ gm,
                           const float* __restrict__ bt, float invcnt) {
    __shared__ float wsum[8];
    const int bn = blockIdx.x;
    const int o  = threadIdx.x;
    const int so = stage*512 + o;
    float mean = g_sum[so] * invcnt;
    float var  = g_ssq[so] * invcnt - mean*mean;
    float a  = gm[o] * rsqrtf(var + 1e-5f);
    float c0 = bt[o] - mean*a;
    long t = (long)bn*O + o;
    float z = (a >= 0.f) ? (a*g_mx[t] + c0) : (a*g_mn[t] + c0);
    z = fmaxf(z, 0.f);
    int b = bn >> 11, n = bn & (N_-1);
    g_xnc[(long)bn*CB + coff + o] = z;
    g_xcn[((long)b*CB + coff + o)*N_ + n] = z;
    float r = z*z;
    #pragma unroll
    for (int d = 16; d; d >>= 1) r += __shfl_xor_sync(0xffffffffu, r, d);
    if ((o & 31) == 0) wsum[o >> 5] = r;
    __syncthreads();
    if (o == 0) {
        float s = 0.f;
        #pragma unroll
        for (int w = 0; w < 8; w++) if (w < (O >> 5)) s += wsum[w];
        g_xx[bn] = s;
    }
}

// ---------------- conv5 stats ----------------
__global__ void __launch_bounds__(512) k_stats5() {
    const int o = threadIdx.x;
    const int p0 = blockIdx.x * 128;
    float s1 = 0.f, s2 = 0.f;
    for (int i = 0; i < 128; i++) {
        float y = g_uv[(long)(p0 + i)*CB + o];
        s1 += y; s2 += y*y;
    }
    atomicAdd(&g_sum[4*512 + o], s1);
    atomicAdd(&g_ssq[4*512 + o], s2);
}

__global__ void k_fin5(const float* __restrict__ gm, const float* __restrict__ bt,
                       float* __restrict__ out) {
    __shared__ float tile[32][33];
    const int b  = blockIdx.z;
    const int o0 = blockIdx.y*32;
    const int n0 = blockIdx.x*32;
    const int tx = threadIdx.x, ty0 = threadIdx.y;
    const float invcnt = 1.f / (float)(B_*N_);
    int o = o0 + tx;
    float mean = g_sum[4*512 + o] * invcnt;
    float var  = g_ssq[4*512 + o] * invcnt - mean*mean;
    float a  = gm[o] * rsqrtf(var + 1e-5f);
    float c0 = bt[o] - mean*a;
    #pragma unroll
    for (int i = 0; i < 4; i++) {
        int ty = ty0 + i*8;
        float y = g_uv[((long)b*N_ + n0 + ty)*CB + o];
        tile[ty][tx] = tanhf(a*y + c0);
    }
    __syncthreads();
    #pragma unroll
    for (int i = 0; i < 4; i++) {
        int ty = ty0 + i*8;
        out[((long)b*CB + o0 + ty)*N_ + n0 + tx] = tile[tx][ty];
    }
}

// ---------------- launch ----------------
extern "C" void kernel_launch(void* const* d_in, const int* in_sizes, int n_in,
                              void* d_out, int out_size) {
    const float* x = (const float*)d_in[0];
    const float* W[5]; const float* G[5]; const float* Bt[5];
    for (int i = 0; i < 5; i++) {
        W[i]  = (const float*)d_in[1 + 3*i];
        G[i]  = (const float*)d_in[2 + 3*i];
        Bt[i] = (const float*)d_in[3 + 3*i];
    }
    float* out = (float*)d_out;

    float* xcn;   cudaGetSymbolAddress((void**)&xcn,  g_xcn);
    float* xnc;   cudaGetSymbolAddress((void**)&xnc,  g_xnc);
    float* x0nc;  cudaGetSymbolAddress((void**)&x0nc, g_x0nc);
    float* uv;    cudaGetSymbolAddress((void**)&uv,   g_uv);
    float4* wt;   cudaGetSymbolAddress((void**)&wt,   g_wT4);

    const int SMK64  = 64*64*4  + 2*16*TNK*4 + 2*TNK*4;   // 33792
    const int SMK128 = 128*64*4 + 2*16*TNK*4 + 2*TNK*4;   // 50176
    cudaFuncSetAttribute(k_knn<64>,  cudaFuncAttributeMaxDynamicSharedMemorySize, SMK64);
    cudaFuncSetAttribute(k_knn<128>, cudaFuncAttributeMaxDynamicSharedMemorySize, SMK128);

    const float invE = 1.f / (float)(B_*N_*K_);
    const dim3 kg(N_/64, B_);
    const int wstart[5] = {0, 128, 2176, 6272, 22656};

    // stage 0 (launch idx 3 = k_knn3w for the profiler slot)
    k_prep_w_all<<<(88192 + 255)/256, 256>>>(W[0], W[1], W[2], W[3], W[4]);
    k_prep_x0<<<(B_*N_ + 255)/256, 256>>>(x);
    k_gemm<64><<<dim3(128, 2), 256>>>(x0nc, 4, 0, 4, 1, wt + wstart[0], 128, uv);
    k_knn3w<<<dim3(N_/32, B_), 256>>>();
    k_edge_max<<<B_*N_/PP, 64>>>(uv, 64, 128, 0);
    k_fin_edge<<<B_*N_, 64>>>(64, 0, 0, G[0], Bt[0], invE);
    // stage 1: C=64 -> O=64
    k_knn<64><<<kg, 128, SMK64>>>(xcn, (long)CB*N_);
    k_gemm<64><<<dim3(128, 2), 256>>>(xnc, CB, 0, 64, 16, wt + wstart[1], 128, uv);
    k_edge_max<<<B_*N_/PP, 64>>>(uv, 64, 128, 1);
    k_fin_edge<<<B_*N_, 64>>>(64, 64, 1, G[1], Bt[1], invE);
    // stage 2: C=64 -> O=128
    k_knn<64><<<kg, 128, SMK64>>>(xcn + (long)64*N_, (long)CB*N_);
    k_gemm<128><<<dim3(128, 2), 256>>>(xnc, CB, 64, 64, 16, wt + wstart[2], 256, uv);
    k_edge_max<<<B_*N_/PP, 128>>>(uv, 128, 256, 2);
    k_fin_edge<<<B_*N_, 128>>>(128, 128, 2, G[2], Bt[2], invE);
    // stage 3: C=128 -> O=256
    k_knn<128><<<kg, 128, SMK128>>>(xcn + (long)128*N_, (long)CB*N_);
    k_gemm<128><<<dim3(128, 4), 256>>>(xnc, CB, 128, 128, 32, wt + wstart[3], 512, uv);
    k_edge_max<<<B_*N_/PP, 256>>>(uv, 256, 512, 3);
    k_fin_edge<<<B_*N_, 256>>>(256, 256, 3, G[3], Bt[3], invE);
    // block 5: 512x512
    k_gemm<128><<<dim3(128, 4), 256>>>(xnc, CB, 0, 512, 128, wt + wstart[4], 512, uv);
    k_stats5<<<128, 512>>>();
    k_fin5<<<dim3(N_/32, CB/32, B_), dim3(32, 8)>>>(G[4], Bt[4], out);
}

// round 9
// speedup vs baseline: 1.3124x; 1.0691x over previous
#include <cuda_runtime.h>
#include <math.h>

#define B_ 8
#define N_ 2048
#define K_ 4
#define CB 512
#define PP 8
#define TNK 128

typedef unsigned long long ull;

#define FFMA2(d,a,b) asm("fma.rn.f32x2 %0, %1, %2, %0;" : "+l"(d) : "l"(a), "l"(b))
#define ADD2(d,a,b)  asm("add.rn.f32x2 %0, %1, %2;" : "=l"(d) : "l"(a), "l"(b))
__device__ __forceinline__ ull pack2(float lo, float hi) {
    ull r; asm("mov.b64 %0, {%1,%2};" : "=l"(r) : "f"(lo), "f"(hi)); return r;
}
__device__ __forceinline__ float2 unpack2(ull v) {
    float2 f; asm("mov.b64 {%0,%1}, %2;" : "=f"(f.x), "=f"(f.y) : "l"(v)); return f;
}

// branchless top-4 insert, strict > (stable: earlier-inserted wins ties)
__device__ __forceinline__ void ins4b(float (&v)[4], int (&ix)[4], float p, int m) {
    float t = p; int ti = m;
    #pragma unroll
    for (int q = 0; q < 4; q++) {
        bool c = t > v[q];
        float vq = v[q]; int iq = ix[q];
        v[q]  = c ? t  : vq;  ix[q] = c ? ti : iq;
        t     = c ? vq : t;   ti    = c ? iq : ti;
    }
}
// branchless lexicographic (val desc, idx asc) — order-independent merge
__device__ __forceinline__ void ins4lexb(float (&v)[4], int (&ix)[4], float p, int m) {
    float t = p; int ti = m;
    #pragma unroll
    for (int q = 0; q < 4; q++) {
        bool c = (t > v[q]) || (t == v[q] && ti < ix[q]);
        float vq = v[q]; int iq = ix[q];
        v[q]  = c ? t  : vq;  ix[q] = c ? ti : iq;
        t     = c ? vq : t;   ti    = c ? iq : ti;
    }
}

// ---------------- scratch ----------------
__device__ float  g_xcn[(size_t)B_*CB*N_];   // [B][C][N]
__device__ float  g_xnc[(size_t)B_*N_*CB];   // [B][N][C]
__device__ float4 g_x0nc[(size_t)B_*N_];     // input [B][N][4], w = ||x||^2
__device__ float  g_xx[(size_t)B_*N_];
__device__ int4   g_idx4[(size_t)B_*N_];
__device__ float  g_uv[(size_t)B_*N_*512];
__device__ float  g_mx[(size_t)B_*N_*256];
__device__ float  g_mn[(size_t)B_*N_*256];
__device__ float  g_sum[5*512];
__device__ float  g_ssq[5*512];
__device__ float4 g_wT4[90112];

// ---------------- prep: pack weights + clear stats ----------------
__global__ void k_prep_w_all(const float* __restrict__ w1, const float* __restrict__ w2,
                             const float* __restrict__ w3, const float* __restrict__ w4,
                             const float* __restrict__ w5) {
    int t = blockIdx.x*blockDim.x + threadIdx.x;
    if (t < 5*512) { g_sum[t] = 0.f; g_ssq[t] = 0.f; }
    if (t >= 88192) return;
    const float* w; int realC, O, parts, lt;
    if      (t < 128)   { w = w1; realC = 3;   O = 64;  parts = 2; lt = t; }
    else if (t < 2176)  { w = w2; realC = 64;  O = 64;  parts = 2; lt = t - 128; }
    else if (t < 6272)  { w = w3; realC = 64;  O = 128; parts = 2; lt = t - 2176; }
    else if (t < 22656) { w = w4; realC = 128; O = 256; parts = 2; lt = t - 6272; }
    else                { w = w5; realC = 512; O = 512; parts = 1; lt = t - 22656; }
    int O2 = parts * O;
    int o2 = lt % O2; int c4 = lt / O2;
    int part = (o2 >= O) ? 1 : 0; int oc = o2 - part*O;
    float4 v; float* pv = (float*)&v;
    #pragma unroll
    for (int j = 0; j < 4; j++) {
        int c = c4*4 + j;
        pv[j] = (c < realC) ? w[oc*(parts*realC) + part*realC + c] : 0.f;
    }
    g_wT4[t] = v;
}

__global__ void k_prep_x0(const float* __restrict__ x) {
    int t = blockIdx.x*blockDim.x + threadIdx.x;
    if (t >= B_*N_) return;
    int b = t >> 11, n = t & (N_-1);
    float vx = x[(b*3+0)*N_ + n];
    float vy = x[(b*3+1)*N_ + n];
    float vz = x[(b*3+2)*N_ + n];
    float xx = fmaf(vz, vz, fmaf(vy, vy, vx*vx));
    g_x0nc[t] = make_float4(vx, vy, vz, xx);
    g_xx[t] = xx;
}

// ---------------- knn C=3: warp-per-4-rows, batch-guarded branchless top-4 ----------------
__global__ void __launch_bounds__(256) k_knn3w() {
    __shared__ float4 pts[N_];               // 32KB: (x,y,z,xx)
    const int b  = blockIdx.y;
    const int n0 = blockIdx.x * 32;
    const int tid = threadIdx.x;
    const int wid = tid >> 5, lane = tid & 31;
    for (int t = tid; t < N_; t += 256) pts[t] = g_x0nc[b*N_ + t];
    __syncthreads();

    const int n = n0 + wid*4;
    float4 P0 = pts[n], P1 = pts[n+1], P2 = pts[n+2], P3 = pts[n+3];
    const ull p01x = pack2(P0.x, P1.x), p23x = pack2(P2.x, P3.x);
    const ull p01y = pack2(P0.y, P1.y), p23y = pack2(P2.y, P3.y);
    const ull p01z = pack2(P0.z, P1.z), p23z = pack2(P2.z, P3.z);
    const ull nr01 = pack2(-P0.w, -P1.w), nr23 = pack2(-P2.w, -P3.w);
    const ull two2 = pack2(2.f, 2.f);

    float cv[4][4]; int ci[4][4];
    #pragma unroll
    for (int r = 0; r < 4; r++)
        #pragma unroll
        for (int q = 0; q < 4; q++) { cv[r][q] = -3.4e38f; ci[r][q] = 0; }

    for (int i8 = 0; i8 < 8; i8++) {
        float2 u01[8], u23[8];
        float bm0 = -3.4e38f, bm1 = -3.4e38f, bm2 = -3.4e38f, bm3 = -3.4e38f;
        #pragma unroll
        for (int j = 0; j < 8; j++) {
            const int m = (i8*8 + j)*32 + lane;
            float4 Q = pts[m];
            ull qx = pack2(Q.x, Q.x), qy = pack2(Q.y, Q.y), qz = pack2(Q.z, Q.z);
            ull nqw = pack2(-Q.w, -Q.w);
            ull a01 = 0ull, a23 = 0ull;
            FFMA2(a01, p01x, qx); FFMA2(a01, p01y, qy); FFMA2(a01, p01z, qz);
            FFMA2(a23, p23x, qx); FFMA2(a23, p23y, qy); FFMA2(a23, p23z, qz);
            ull t01 = nr01; FFMA2(t01, a01, two2);
            ull t23 = nr23; FFMA2(t23, a23, two2);
            ull pd01; ADD2(pd01, t01, nqw);
            ull pd23; ADD2(pd23, t23, nqw);
            u01[j] = unpack2(pd01); u23[j] = unpack2(pd23);
            bm0 = fmaxf(bm0, u01[j].x); bm1 = fmaxf(bm1, u01[j].y);
            bm2 = fmaxf(bm2, u23[j].x); bm3 = fmaxf(bm3, u23[j].y);
        }
        bool need = (bm0 > cv[0][3]) | (bm1 > cv[1][3]) |
                    (bm2 > cv[2][3]) | (bm3 > cv[3][3]);
        if (need) {
            #pragma unroll
            for (int j = 0; j < 8; j++) {
                const int m = (i8*8 + j)*32 + lane;
                ins4b(cv[0], ci[0], u01[j].x, m);
                ins4b(cv[1], ci[1], u01[j].y, m);
                ins4b(cv[2], ci[2], u23[j].x, m);
                ins4b(cv[3], ci[3], u23[j].y, m);
            }
        }
    }
    #pragma unroll
    for (int st = 1; st <= 16; st <<= 1) {
        #pragma unroll
        for (int r = 0; r < 4; r++) {
            float pv[4]; int pi[4];
            #pragma unroll
            for (int q = 0; q < 4; q++) {
                pv[q] = __shfl_xor_sync(0xffffffffu, cv[r][q], st);
                pi[q] = __shfl_xor_sync(0xffffffffu, ci[r][q], st);
            }
            #pragma unroll
            for (int q = 0; q < 4; q++) ins4lexb(cv[r], ci[r], pv[q], pi[q]);
        }
    }
    if (lane == 0) {
        #pragma unroll
        for (int r = 0; r < 4; r++)
            g_idx4[b*N_ + n + r] = make_int4(ci[r][0], ci[r][1], ci[r][2], ci[r][3]);
    }
}

// ---------------- knn C=64/128: natural-B tiles, rowmax-guarded scan ----------------
template<int C>
__global__ void __launch_bounds__(128) k_knn(const float* __restrict__ base, long bstride) {
    constexpr int KCc = 16;
    constexpr int NCH = C / KCc;
    constexpr int TM  = 64;
    constexpr int NG  = (N_/TNK)*NCH;
    extern __shared__ char smraw[];
    float* Ash = (float*)smraw;                                   // [C][TM]
    float* Bsh = (float*)(smraw + (size_t)C*TM*4);                // [2][KCc][TNK]
    float* xxs = (float*)(smraw + (size_t)C*TM*4 + 2*KCc*TNK*4);  // [2][TNK]
    const int b  = blockIdx.y;
    const int n0 = blockIdx.x * TM;
    const float* X = base + (long)b*bstride;
    const float* xxg = g_xx + b*N_;
    const int tid = threadIdx.x;
    const int ty = tid >> 3, tx = tid & 7;
    const int r0 = ty*4;
    const int c0 = 2*tx;

    for (int t = tid; t < C*TM; t += 128) {
        int c = t >> 6, r = t & 63;
        Ash[t] = X[(long)c*N_ + n0 + r];
    }
    float xxr[4];
    #pragma unroll
    for (int i = 0; i < 4; i++) xxr[i] = xxg[n0 + r0 + i];

    float cv[4][4]; int ci[4][4];
    #pragma unroll
    for (int r = 0; r < 4; r++)
        #pragma unroll
        for (int q = 0; q < 4; q++) { cv[r][q] = -3.4e38f; ci[r][q] = 0; }

    for (int t = tid; t < KCc*TNK; t += 128) {
        int c = t >> 7, m = t & 127;
        Bsh[t] = X[(long)c*N_ + m];
    }
    xxs[tid] = xxg[tid];
    __syncthreads();

    ull acc[4][8];
    #pragma unroll
    for (int i = 0; i < 4; i++)
        #pragma unroll
        for (int k = 0; k < 8; k++) acc[i][k] = 0ull;

    for (int g = 0; g < NG; g++) {
        const int mb = g / NCH, ch = g - mb*NCH;
        if (g + 1 < NG) {
            const int g1 = g + 1;
            const int mb1 = g1 / NCH, ch1 = g1 - mb1*NCH;
            const int m01 = mb1*TNK;
            float* bd = Bsh + (g1 & 1)*(KCc*TNK);
            #pragma unroll
            for (int t = tid; t < KCc*TNK; t += 128) {
                int c = t >> 7, m = t & 127;
                bd[t] = X[(long)(ch1*KCc + c)*N_ + m01 + m];
            }
            if (ch1 == 0) xxs[(mb1 & 1)*TNK + tid] = xxg[m01 + tid];
        }
        const float* bb = Bsh + (g & 1)*(KCc*TNK);
        #pragma unroll
        for (int cc = 0; cc < KCc; cc++) {
            float4 a4 = *(const float4*)&Ash[(ch*KCc + cc)*TM + r0];
            ull ad0 = pack2(a4.x, a4.x);
            ull ad1 = pack2(a4.y, a4.y);
            ull ad2 = pack2(a4.z, a4.z);
            ull ad3 = pack2(a4.w, a4.w);
            const ull* bp = (const ull*)&bb[cc*TNK];
            #pragma unroll
            for (int k = 0; k < 8; k++) {
                ull bpair = bp[k*8 + tx];
                FFMA2(acc[0][k], ad0, bpair);
                FFMA2(acc[1][k], ad1, bpair);
                FFMA2(acc[2][k], ad2, bpair);
                FFMA2(acc[3][k], ad3, bpair);
            }
        }
        if (ch == NCH - 1) {
            const float* xxb = xxs + (mb & 1)*TNK;
            const int m0 = mb*TNK;
            float xcl[16];
            #pragma unroll
            for (int k = 0; k < 8; k++) {
                float2 x2 = *(const float2*)&xxb[16*k + c0];
                xcl[2*k] = x2.x; xcl[2*k+1] = x2.y;
            }
            #pragma unroll
            for (int i = 0; i < 4; i++) {
                float pd[16];
                float rmax = -3.4e38f;
                #pragma unroll
                for (int k = 0; k < 8; k++) {
                    float2 u = unpack2(acc[i][k]);
                    float p0 = fmaf(2.f, u.x, -xxr[i]) - xcl[2*k];
                    float p1 = fmaf(2.f, u.y, -xxr[i]) - xcl[2*k+1];
                    pd[2*k] = p0; pd[2*k+1] = p1;
                    rmax = fmaxf(rmax, fmaxf(p0, p1));
                    acc[i][k] = 0ull;
                }
                if (rmax > cv[i][3]) {
                    #pragma unroll
                    for (int k = 0; k < 16; k++)
                        ins4b(cv[i], ci[i], pd[k], m0 + 16*(k >> 1) + c0 + (k & 1));
                }
            }
        }
        __syncthreads();
    }
    #pragma unroll
    for (int st = 1; st <= 4; st <<= 1) {
        #pragma unroll
        for (int r = 0; r < 4; r++) {
            float pv[4]; int pi[4];
            #pragma unroll
            for (int q = 0; q < 4; q++) {
                pv[q] = __shfl_xor_sync(0xffffffffu, cv[r][q], st);
                pi[q] = __shfl_xor_sync(0xffffffffu, ci[r][q], st);
            }
            #pragma unroll
            for (int q = 0; q < 4; q++) ins4lexb(cv[r], ci[r], pv[q], pi[q]);
        }
    }
    if (tx == 0) {
        #pragma unroll
        for (int r = 0; r < 4; r++)
            g_idx4[b*N_ + n0 + r0 + r] = make_int4(ci[r][0], ci[r][1], ci[r][2], ci[r][3]);
    }
}

// ---------------- generic GEMM (column-packed accs, natural B, dup-A) ----------------
template<int TN>
__global__ void __launch_bounds__(256) k_gemm(const float* __restrict__ src, int CS, int coff,
                                              int C, int c4n, const float4* __restrict__ wb,
                                              int O2, float* __restrict__ out) {
    constexpr int CP = TN/32;                 // column-pairs per thread
    __shared__ float Ash[16*132];
    __shared__ float Bsh[16*TN];
    const int pt0 = blockIdx.x * 128;
    const int ob0 = blockIdx.y * TN;
    const int tid = threadIdx.x;
    const int ty = tid >> 4, tx = tid & 15;
    const int r0 = ty*8;

    ull acc[8][CP];
    #pragma unroll
    for (int p = 0; p < 8; p++)
        #pragma unroll
        for (int j = 0; j < CP; j++) acc[p][j] = 0ull;

    const int C16 = (C + 15) & ~15;
    for (int kc = 0; kc < C16; kc += 16) {
        #pragma unroll
        for (int t = tid; t < 16*128; t += 256) {
            int c = t & 15, r = t >> 4;
            float v = (kc + c < C) ? src[(long)(pt0 + r)*CS + coff + kc + c] : 0.f;
            Ash[c*132 + r] = v;
        }
        #pragma unroll
        for (int t = tid; t < 4*TN; t += 256) {
            int q = t / TN, o = t - q*TN;
            int c4 = (kc >> 2) + q;
            float4 w = (c4 < c4n) ? wb[(long)c4*O2 + ob0 + o] : make_float4(0.f,0.f,0.f,0.f);
            Bsh[(4*q+0)*TN + o] = w.x;
            Bsh[(4*q+1)*TN + o] = w.y;
            Bsh[(4*q+2)*TN + o] = w.z;
            Bsh[(4*q+3)*TN + o] = w.w;
        }
        __syncthreads();
        #pragma unroll
        for (int cc = 0; cc < 16; cc++) {
            float4 aA = *(const float4*)&Ash[cc*132 + r0];
            float4 aB = *(const float4*)&Ash[cc*132 + r0 + 4];
            ull ad[8];
            ad[0] = pack2(aA.x, aA.x); ad[1] = pack2(aA.y, aA.y);
            ad[2] = pack2(aA.z, aA.z); ad[3] = pack2(aA.w, aA.w);
            ad[4] = pack2(aB.x, aB.x); ad[5] = pack2(aB.y, aB.y);
            ad[6] = pack2(aB.z, aB.z); ad[7] = pack2(aB.w, aB.w);
            const ull* bp = (const ull*)&Bsh[cc*TN] + tx;
            #pragma unroll
            for (int j = 0; j < CP; j++) {
                ull bb = bp[j*16];
                #pragma unroll
                for (int p = 0; p < 8; p++) FFMA2(acc[p][j], ad[p], bb);
            }
        }
        __syncthreads();
    }
    #pragma unroll
    for (int p = 0; p < 8; p++) {
        long rowL = (long)(pt0 + r0 + p) * O2 + ob0 + 2*tx;
        #pragma unroll
        for (int j = 0; j < CP; j++) {
            float2 u = unpack2(acc[p][j]);
            *(float2*)&out[rowL + j*32] = u;
        }
    }
}

// ---------------- gather + minmax over k + stats ----------------
__global__ void k_edge_max(const float* __restrict__ uv, int O, int O2, int stage) {
    __shared__ int sidx[PP*K_];
    const int blk = blockIdx.x;
    const int pt0 = blk * PP;
    const int o = threadIdx.x;
    const int b = pt0 >> 11;
    if (o < PP) ((int4*)sidx)[o] = g_idx4[pt0 + o];
    __syncthreads();
    float s1 = 0.f, s2 = 0.f;
    #pragma unroll
    for (int p = 0; p < PP; p++) {
        float v = uv[(long)(pt0 + p)*O2 + O + o];
        float mx = -3.4e38f, mn = 3.4e38f;
        #pragma unroll
        for (int k = 0; k < K_; k++) {
            int nb = sidx[p*K_ + k];
            float u = uv[(long)(b*N_ + nb)*O2 + o];
            float y = u + v;
            mx = fmaxf(mx, y); mn = fminf(mn, y);
            s1 += y; s2 += y*y;
        }
        g_mx[(long)(pt0 + p)*O + o] = mx;
        g_mn[(long)(pt0 + p)*O + o] = mn;
    }
    atomicAdd(&g_sum[stage*512 + o], s1);
    atomicAdd(&g_ssq[stage*512 + o], s2);
}

// ---------------- BN finalize + relu + both layouts + next-stage norms ----------------
__global__ void k_fin_edge(int O, int coff, int stage, const float* __restrict__ gm,
                           const float* __restrict__ bt, float invcnt) {
    __shared__ float wsum[8];
    const int bn = blockIdx.x;
    const int o  = threadIdx.x;
    const int so = stage*512 + o;
    float mean = g_sum[so] * invcnt;
    float var  = g_ssq[so] * invcnt - mean*mean;
    float a  = gm[o] * rsqrtf(var + 1e-5f);
    float c0 = bt[o] - mean*a;
    long t = (long)bn*O + o;
    float z = (a >= 0.f) ? (a*g_mx[t] + c0) : (a*g_mn[t] + c0);
    z = fmaxf(z, 0.f);
    int b = bn >> 11, n = bn & (N_-1);
    g_xnc[(long)bn*CB + coff + o] = z;
    g_xcn[((long)b*CB + coff + o)*N_ + n] = z;
    float r = z*z;
    #pragma unroll
    for (int d = 16; d; d >>= 1) r += __shfl_xor_sync(0xffffffffu, r, d);
    if ((o & 31) == 0) wsum[o >> 5] = r;
    __syncthreads();
    if (o == 0) {
        float s = 0.f;
        #pragma unroll
        for (int w = 0; w < 8; w++) if (w < (O >> 5)) s += wsum[w];
        g_xx[bn] = s;
    }
}

// ---------------- conv5 stats ----------------
__global__ void __launch_bounds__(512) k_stats5() {
    const int o = threadIdx.x;
    const int p0 = blockIdx.x * 128;
    float s1 = 0.f, s2 = 0.f;
    for (int i = 0; i < 128; i++) {
        float y = g_uv[(long)(p0 + i)*CB + o];
        s1 += y; s2 += y*y;
    }
    atomicAdd(&g_sum[4*512 + o], s1);
    atomicAdd(&g_ssq[4*512 + o], s2);
}

__global__ void k_fin5(const float* __restrict__ gm, const float* __restrict__ bt,
                       float* __restrict__ out) {
    __shared__ float tile[32][33];
    const int b  = blockIdx.z;
    const int o0 = blockIdx.y*32;
    const int n0 = blockIdx.x*32;
    const int tx = threadIdx.x, ty0 = threadIdx.y;
    const float invcnt = 1.f / (float)(B_*N_);
    int o = o0 + tx;
    float mean = g_sum[4*512 + o] * invcnt;
    float var  = g_ssq[4*512 + o] * invcnt - mean*mean;
    float a  = gm[o] * rsqrtf(var + 1e-5f);
    float c0 = bt[o] - mean*a;
    #pragma unroll
    for (int i = 0; i < 4; i++) {
        int ty = ty0 + i*8;
        float y = g_uv[((long)b*N_ + n0 + ty)*CB + o];
        tile[ty][tx] = tanhf(a*y + c0);
    }
    __syncthreads();
    #pragma unroll
    for (int i = 0; i < 4; i++) {
        int ty = ty0 + i*8;
        out[((long)b*CB + o0 + ty)*N_ + n0 + tx] = tile[tx][ty];
    }
}

// ---------------- launch ----------------
extern "C" void kernel_launch(void* const* d_in, const int* in_sizes, int n_in,
                              void* d_out, int out_size) {
    const float* x = (const float*)d_in[0];
    const float* W[5]; const float* G[5]; const float* Bt[5];
    for (int i = 0; i < 5; i++) {
        W[i]  = (const float*)d_in[1 + 3*i];
        G[i]  = (const float*)d_in[2 + 3*i];
        Bt[i] = (const float*)d_in[3 + 3*i];
    }
    float* out = (float*)d_out;

    float* xcn;   cudaGetSymbolAddress((void**)&xcn,  g_xcn);
    float* xnc;   cudaGetSymbolAddress((void**)&xnc,  g_xnc);
    float* x0nc;  cudaGetSymbolAddress((void**)&x0nc, g_x0nc);
    float* uv;    cudaGetSymbolAddress((void**)&uv,   g_uv);
    float4* wt;   cudaGetSymbolAddress((void**)&wt,   g_wT4);

    const int SMK64  = 64*64*4  + 2*16*TNK*4 + 2*TNK*4;   // 33792
    const int SMK128 = 128*64*4 + 2*16*TNK*4 + 2*TNK*4;   // 50176
    cudaFuncSetAttribute(k_knn<64>,  cudaFuncAttributeMaxDynamicSharedMemorySize, SMK64);
    cudaFuncSetAttribute(k_knn<128>, cudaFuncAttributeMaxDynamicSharedMemorySize, SMK128);

    const float invE = 1.f / (float)(B_*N_*K_);
    const dim3 kg(N_/64, B_);
    const int wstart[5] = {0, 128, 2176, 6272, 22656};

    // stage 0 (launch idx 3 = k_knn3w for the profiler slot)
    k_prep_w_all<<<(88192 + 255)/256, 256>>>(W[0], W[1], W[2], W[3], W[4]);
    k_prep_x0<<<(B_*N_ + 255)/256, 256>>>(x);
    k_gemm<64><<<dim3(128, 2), 256>>>(x0nc, 4, 0, 4, 1, wt + wstart[0], 128, uv);
    k_knn3w<<<dim3(N_/32, B_), 256>>>();
    k_edge_max<<<B_*N_/PP, 64>>>(uv, 64, 128, 0);
    k_fin_edge<<<B_*N_, 64>>>(64, 0, 0, G[0], Bt[0], invE);
    // stage 1: C=64 -> O=64
    k_knn<64><<<kg, 128, SMK64>>>(xcn, (long)CB*N_);
    k_gemm<64><<<dim3(128, 2), 256>>>(xnc, CB, 0, 64, 16, wt + wstart[1], 128, uv);
    k_edge_max<<<B_*N_/PP, 64>>>(uv, 64, 128, 1);
    k_fin_edge<<<B_*N_, 64>>>(64, 64, 1, G[1], Bt[1], invE);
    // stage 2: C=64 -> O=128
    k_knn<64><<<kg, 128, SMK64>>>(xcn + (long)64*N_, (long)CB*N_);
    k_gemm<128><<<dim3(128, 2), 256>>>(xnc, CB, 64, 64, 16, wt + wstart[2], 256, uv);
    k_edge_max<<<B_*N_/PP, 128>>>(uv, 128, 256, 2);
    k_fin_edge<<<B_*N_, 128>>>(128, 128, 2, G[2], Bt[2], invE);
    // stage 3: C=128 -> O=256
    k_knn<128><<<kg, 128, SMK128>>>(xcn + (long)128*N_, (long)CB*N_);
    k_gemm<128><<<dim3(128, 4), 256>>>(xnc, CB, 128, 128, 32, wt + wstart[3], 512, uv);
    k_edge_max<<<B_*N_/PP, 256>>>(uv, 256, 512, 3);
    k_fin_edge<<<B_*N_, 256>>>(256, 256, 3, G[3], Bt[3], invE);
    // block 5: 512x512
    k_gemm<128><<<dim3(128, 4), 256>>>(xnc, CB, 0, 512, 128, wt + wstart[4], 512, uv);
    k_stats5<<<128, 512>>>();
    k_fin5<<<dim3(N_/32, CB/32, B_), dim3(32, 8)>>>(G[4], Bt[4], out);
}